// round 13
// baseline (speedup 1.0000x reference)
#include <cuda_runtime.h>
#include <cuda_fp16.h>
#include <math_constants.h>
#include <cstdint>

// VectorQuantizer: 1-pass fp16 hi*hi mma.sync filter + exact fp32 rescore.
// latents [65536,64] f32, embedding [512,64] f32.
// out[0] = vq_loss, out[1..] = quantized_st (4B-aligned only -> scalar stores).
//
// Filter: h = b - S/256 with S = sum hi16(x)*hi16(512e) (fp32 accum);
// |h - (dist - a)| <= 2.1e-4 worst case -> any potentially-winning col obeys
// h <= runningMin + 4.2e-4; BAND = 1e-3 gives 2.4x margin. Collected cols are
// rescored EXACTLY (R1-validated fmaf chain, fl(fl(a+b)-2c), first-index ties).
// R13 fix: minEnc must init to fenc(+inf) -- 0xFFFFFFFF decoded to NaN, which
// killed collection at nt=0 and produced garbage indices for ~1.6% of rows.

#define NROWS 65536
#define KEMB 512
#define DDIM 64
#define TILE_M 64
#define NCTAS (NROWS / TILE_M)   // 1024
#define NTHREADS 128             // 4 warps; warp owns 16 rows (1 m16 tile)
#define NT_TILES (KEMB / 8)      // 64
#define KT 4                     // K = 64 = 4 x k16
#define CAP 32
#define BAND 1e-3f

__device__ uint2  g_epack[KT * KEMB * 4];  // 64 KB: B cells (hi only)
__device__ float  g_bn[KEMB];              // ||e||^2 exact chains
__device__ double g_part[NCTAS];
__device__ int    g_cnt = 0;               // last-CTA ticket (self-resetting)

__device__ __forceinline__ uint32_t pack_h2(__half lo, __half hi) {
    return (uint32_t)__half_as_ushort(lo) | ((uint32_t)__half_as_ushort(hi) << 16);
}
__device__ __forceinline__ void mma_f16(float* d, const uint4 a,
                                        uint32_t b0, uint32_t b1) {
    asm volatile(
        "mma.sync.aligned.m16n8k16.row.col.f32.f16.f16.f32 "
        "{%0,%1,%2,%3}, {%4,%5,%6,%7}, {%8,%9}, {%0,%1,%2,%3};"
        : "+f"(d[0]), "+f"(d[1]), "+f"(d[2]), "+f"(d[3])
        : "r"(a.x), "r"(a.y), "r"(a.z), "r"(a.w), "r"(b0), "r"(b1));
}
// order-preserving float<->uint encoding (works for negatives)
__device__ __forceinline__ unsigned fenc(float f) {
    int i = __float_as_int(f);
    return (i >= 0) ? ((unsigned)i | 0x80000000u) : ~(unsigned)i;
}
__device__ __forceinline__ float fdec(unsigned k) {
    return (k & 0x80000000u) ? __int_as_float((int)(k & 0x7FFFFFFFu))
                             : __int_as_float((int)~k);
}
// exact R1-class distance: sequential fmaf chain + fl(fl(a+b) - 2c)
__device__ __forceinline__ float exact_dist(const float* __restrict__ x,
                                            const float* __restrict__ e,
                                            float a, float b) {
    float c = 0.f;
    #pragma unroll
    for (int d = 0; d < DDIM; d++)
        c = __fmaf_rn(__ldg(x + d), __ldg(e + d), c);
    return __fsub_rn(__fadd_rn(a, b), 2.0f * c);
}

// ---------------- pre-kernel (8 blocks): E hi-cells + ||e||^2 ----------------
__global__ __launch_bounds__(128)
void vq_epack_kernel(const float* __restrict__ emb) {
    const int tid = threadIdx.x;
    const int b = blockIdx.x;
    if (tid < 64) {                 // Bn: sequential fp32 chain on raw e
        int n = b * 64 + tid;
        const float* e = emb + (size_t)n * DDIM;
        float s = 0.f;
        #pragma unroll
        for (int d = 0; d < DDIM; d++)
            s = __fadd_rn(s, __fmul_rn(e[d], e[d]));
        g_bn[n] = s;
    }
    #pragma unroll
    for (int s = 0; s < 8; s++) {
        int ci = s * 128 + tid;
        int kt = ci >> 8, rem = ci & 255;
        int nl = rem >> 2, qs = rem & 3;
        int n = b * 64 + nl;
        int k0 = kt * 16 + 2 * qs;
        float2 e01 = __ldg((const float2*)(emb + (size_t)n * DDIM + k0));
        float2 e89 = __ldg((const float2*)(emb + (size_t)n * DDIM + k0 + 8));
        __half h0 = __float2half_rn(512.f * e01.x);
        __half h1 = __float2half_rn(512.f * e01.y);
        __half h2 = __float2half_rn(512.f * e89.x);
        __half h3 = __float2half_rn(512.f * e89.y);
        g_epack[(kt * KEMB + n) * 4 + qs] = make_uint2(pack_h2(h0, h1), pack_h2(h2, h3));
    }
}

// ---------------- main kernel ----------------
__global__ __launch_bounds__(NTHREADS)
void vq_mma_kernel(const float* __restrict__ lat,
                   const float* __restrict__ emb,
                   float* __restrict__ out /* d_out; quant = out+1 */)
{
    __shared__ float    BnS[KEMB];
    __shared__ float    AsS[TILE_M];
    __shared__ unsigned minEnc[TILE_M];
    __shared__ int      cnt[TILE_M];
    __shared__ int      lst[TILE_M][CAP];
    __shared__ unsigned long long mkey[TILE_M];
    __shared__ int      IdxS[TILE_M];
    __shared__ double   Wsum[4];
    __shared__ int      lastFlag;

    float* quant = out + 1;

    const int tid  = threadIdx.x;
    const int w    = tid >> 5;
    const int lane = tid & 31;
    const int qid  = lane >> 2;
    const int qsub = lane & 3;
    const int rowBase = blockIdx.x * TILE_M;

    #pragma unroll
    for (int i = 0; i < 4; i++) BnS[i * NTHREADS + tid] = g_bn[i * NTHREADS + tid];
    if (tid < TILE_M) {
        // a = ||x||^2: sequential fp32 chain (must match reference grid)
        const float* x = lat + (size_t)(rowBase + tid) * DDIM;
        float s = 0.f;
        #pragma unroll
        for (int d = 0; d < DDIM; d++)
            s = __fadd_rn(s, __fmul_rn(__ldg(x + d), __ldg(x + d)));
        AsS[tid] = s;
        minEnc[tid] = fenc(CUDART_INF_F);   // R13 FIX: decodes to +inf, not NaN
        cnt[tid] = 0;
        mkey[tid] = ~0ull;
    }

    // ---- A fragments: hi halves only (LDG + in-register convert) ----
    uint4 AH[KT];
    {
        const size_t r0 = (size_t)(rowBase + w * 16 + qid) * DDIM;
        const size_t r1 = r0 + 8 * DDIM;
        #pragma unroll
        for (int kt = 0; kt < KT; kt++) {
            const int k0 = kt * 16 + 2 * qsub;
            float2 x00 = __ldg((const float2*)(lat + r0 + k0));
            float2 x10 = __ldg((const float2*)(lat + r1 + k0));
            float2 x02 = __ldg((const float2*)(lat + r0 + k0 + 8));
            float2 x12 = __ldg((const float2*)(lat + r1 + k0 + 8));
            AH[kt] = make_uint4(
                pack_h2(__float2half_rn(x00.x), __float2half_rn(x00.y)),
                pack_h2(__float2half_rn(x10.x), __float2half_rn(x10.y)),
                pack_h2(__float2half_rn(x02.x), __float2half_rn(x02.y)),
                pack_h2(__float2half_rn(x12.x), __float2half_rn(x12.y)));
        }
    }
    __syncthreads();

    // ---- pass 1: 4 MMAs per nt; band-collect candidates ----
    #pragma unroll 2
    for (int nt = 0; nt < NT_TILES; nt++) {
        uint2 Bc[KT];
        #pragma unroll
        for (int kt = 0; kt < KT; kt++)
            Bc[kt] = __ldg(&g_epack[(kt * KEMB + nt * 8 + qid) * 4 + qsub]);

        float s[4] = {0.f, 0.f, 0.f, 0.f};
        #pragma unroll
        for (int kt = 0; kt < KT; kt++)
            mma_f16(s, AH[kt], Bc[kt].x, Bc[kt].y);

        const int col0 = nt * 8 + qsub * 2;
        const float b0 = BnS[col0], b1 = BnS[col0 + 1];
        #pragma unroll
        for (int j = 0; j < 2; j++) {
            const int rowL = w * 16 + j * 8 + qid;
            float h0 = __fmaf_rn(s[j * 2],     -0.00390625f, b0);
            float h1 = __fmaf_rn(s[j * 2 + 1], -0.00390625f, b1);
            unsigned me = minEnc[rowL];
            float thr = fdec(me) + BAND;
            if (h0 <= thr) {
                int p = atomicAdd(&cnt[rowL], 1);
                if (p < CAP) lst[rowL][p] = col0;
            }
            if (h1 <= thr) {
                int p = atomicAdd(&cnt[rowL], 1);
                if (p < CAP) lst[rowL][p] = col0 + 1;
            }
            unsigned ke = fenc(fminf(h0, h1));
            if (ke < me) atomicMin(&minEnc[rowL], ke);
        }
    }
    __syncthreads();

    // ---- phase 2: exact rescore of band candidates ----
    {
        const int row = tid >> 1, half = tid & 1;
        const float* x = lat + (size_t)(rowBase + row) * DDIM;
        const float a = AsS[row];
        const int n = min(cnt[row], CAP);
        for (int i = half; i < n; i += 2) {
            int col = lst[row][i];
            float d = exact_dist(x, emb + (size_t)col * DDIM, a, BnS[col]);
            unsigned long long key = ((unsigned long long)__float_as_uint(d) << 32)
                                     | (unsigned)col;
            atomicMin(&mkey[row], key);
        }
    }
    __syncthreads();
    // overflow fallback (sound even if the list overflowed): full-row rescan
    for (int r = 0; r < TILE_M; r++) {
        if (cnt[r] > CAP) {
            const float* x = lat + (size_t)(rowBase + r) * DDIM;
            const float a = AsS[r];
            for (int col = tid; col < KEMB; col += NTHREADS) {
                float d = exact_dist(x, emb + (size_t)col * DDIM, a, BnS[col]);
                unsigned long long key = ((unsigned long long)__float_as_uint(d) << 32)
                                         | (unsigned)col;
                atomicMin(&mkey[r], key);
            }
        }
    }
    __syncthreads();
    if (tid < TILE_M) IdxS[tid] = (int)(mkey[tid] & 0xFFFFFFFFull);
    __syncthreads();

    // ---- gather + straight-through write (scalar stores) + fp64 loss ----
    double ls = 0.0;
    {
        const int seg  = tid & 15;
        const int rsub = tid >> 4;
        #pragma unroll
        for (int p = 0; p < 8; p++) {
            int row = p * 8 + rsub;
            int idx = IdxS[row];
            float4 q = __ldg((const float4*)(emb + (size_t)idx * DDIM + seg * 4));
            float4 l = __ldg((const float4*)(lat + (size_t)(rowBase + row) * DDIM + seg * 4));
            float t0 = q.x - l.x, t1 = q.y - l.y, t2 = q.z - l.z, t3 = q.w - l.w;
            ls += (double)t0 * t0 + (double)t1 * t1
                + (double)t2 * t2 + (double)t3 * t3;
            float* o = quant + (size_t)(rowBase + row) * DDIM + seg * 4;
            o[0] = l.x + t0;
            o[1] = l.y + t1;
            o[2] = l.z + t2;
            o[3] = l.w + t3;
        }
    }

    #pragma unroll
    for (int off = 16; off >= 1; off >>= 1)
        ls += __shfl_xor_sync(0xffffffffu, ls, off);
    if (lane == 0) Wsum[w] = ls;
    __syncthreads();

    // ---- publish partial, then last CTA reduces (deterministic order) ----
    if (tid == 0) {
        g_part[blockIdx.x] = Wsum[0] + Wsum[1] + Wsum[2] + Wsum[3];
        __threadfence();
        int ticket = atomicAdd(&g_cnt, 1);
        lastFlag = (ticket == NCTAS - 1) ? 1 : 0;
    }
    __syncthreads();
    if (lastFlag) {
        double s = 0.0;
        #pragma unroll
        for (int i = 0; i < NCTAS / NTHREADS; i++)     // fixed order: 8 per thread
            s += g_part[i * NTHREADS + tid];
        #pragma unroll
        for (int off = 16; off >= 1; off >>= 1)
            s += __shfl_xor_sync(0xffffffffu, s, off);
        if (lane == 0) Wsum[w] = s;
        __syncthreads();
        if (tid == 0) {
            double m = (Wsum[0] + Wsum[1] + Wsum[2] + Wsum[3])
                       / (double)((size_t)NROWS * DDIM);
            out[0] = (float)(1.25 * m);
            g_cnt = 0;   // self-reset for graph replay
        }
    }
}

extern "C" void kernel_launch(void* const* d_in, const int* in_sizes, int n_in,
                              void* d_out, int out_size) {
    const float* lat = (const float*)d_in[0];   // latents  [65536, 64]
    const float* emb = (const float*)d_in[1];   // embedding [512, 64]
    float* out = (float*)d_out;

    vq_epack_kernel<<<8, 128>>>(emb);
    vq_mma_kernel<<<NCTAS, NTHREADS>>>(lat, emb, out);
}

// round 14
// speedup vs baseline: 1.4932x; 1.4932x over previous
#include <cuda_runtime.h>
#include <cuda_fp16.h>
#include <math_constants.h>
#include <cstdint>

// VectorQuantizer: 1-pass fp16 hi*hi mma.sync filter + exact fp32 rescore.
// latents [65536,64] f32, embedding [512,64] f32.
// out[0] = vq_loss, out[1..] = quantized_st (4B-aligned only -> scalar stores).
//
// Filter: h = b - S/256, S = sum hi16(x)*hi16(512e) (fp32 accum).
// |h - (dist - a)| <= 2.4e-4 worst case -> winning col obeys h <= gmin+4.8e-4;
// BAND = 1e-3 gives 2x margin. R14: candidates tracked as per-thread REGISTER
// top-3 (R13's shared-memory collection cost 3x the MMA savings). If a thread's
// min3 < gmin+BAND its coverage is incomplete -> row flagged, exact full rescan
// (sound by construction). Survivors rescored with the R1-validated ascending
// fmaf chain; fl(fl(a+b)-2c); first-index ties via packed-key atomicMin.

#define NROWS 65536
#define KEMB 512
#define DDIM 64
#define TILE_M 64
#define NCTAS (NROWS / TILE_M)   // 1024
#define NTHREADS 128             // 4 warps; warp owns 16 rows (1 m16 tile)
#define NT_TILES (KEMB / 8)      // 64
#define KT 4                     // K = 64 = 4 x k16
#define BAND 1e-3f

__device__ uint2  g_epack[KT * KEMB * 4];  // 64 KB: B cells (hi only)
__device__ float  g_bn[KEMB];              // ||e||^2 exact chains
__device__ double g_part[NCTAS];
__device__ int    g_cnt = 0;               // last-CTA ticket (self-resetting)

__device__ __forceinline__ uint32_t pack_h2(__half lo, __half hi) {
    return (uint32_t)__half_as_ushort(lo) | ((uint32_t)__half_as_ushort(hi) << 16);
}
__device__ __forceinline__ void mma_f16(float* d, const uint4 a,
                                        uint32_t b0, uint32_t b1) {
    asm volatile(
        "mma.sync.aligned.m16n8k16.row.col.f32.f16.f16.f32 "
        "{%0,%1,%2,%3}, {%4,%5,%6,%7}, {%8,%9}, {%0,%1,%2,%3};"
        : "+f"(d[0]), "+f"(d[1]), "+f"(d[2]), "+f"(d[3])
        : "r"(a.x), "r"(a.y), "r"(a.z), "r"(a.w), "r"(b0), "r"(b1));
}
// exact R1-class distance: ascending-d fmaf chain + fl(fl(a+b) - 2c).
// float4 loads keep the identical per-element accumulation order.
__device__ __forceinline__ float exact_dist4(const float* __restrict__ x,
                                             const float* __restrict__ e,
                                             float a, float b) {
    float c = 0.f;
    #pragma unroll
    for (int d = 0; d < DDIM; d += 4) {
        float4 xv = *(const float4*)(x + d);
        float4 ev = __ldg((const float4*)(e + d));
        c = __fmaf_rn(xv.x, ev.x, c);
        c = __fmaf_rn(xv.y, ev.y, c);
        c = __fmaf_rn(xv.z, ev.z, c);
        c = __fmaf_rn(xv.w, ev.w, c);
    }
    return __fsub_rn(__fadd_rn(a, b), 2.0f * c);
}

// ---------------- pre-kernel (8 blocks): E hi-cells + ||e||^2 ----------------
__global__ __launch_bounds__(128)
void vq_epack_kernel(const float* __restrict__ emb) {
    const int tid = threadIdx.x;
    const int b = blockIdx.x;
    if (tid < 64) {                 // Bn: sequential fp32 chain on raw e
        int n = b * 64 + tid;
        const float* e = emb + (size_t)n * DDIM;
        float s = 0.f;
        #pragma unroll
        for (int d = 0; d < DDIM; d++)
            s = __fadd_rn(s, __fmul_rn(e[d], e[d]));
        g_bn[n] = s;
    }
    #pragma unroll
    for (int s = 0; s < 8; s++) {
        int ci = s * 128 + tid;
        int kt = ci >> 8, rem = ci & 255;
        int nl = rem >> 2, qs = rem & 3;
        int n = b * 64 + nl;
        int k0 = kt * 16 + 2 * qs;
        float2 e01 = __ldg((const float2*)(emb + (size_t)n * DDIM + k0));
        float2 e89 = __ldg((const float2*)(emb + (size_t)n * DDIM + k0 + 8));
        __half h0 = __float2half_rn(512.f * e01.x);
        __half h1 = __float2half_rn(512.f * e01.y);
        __half h2 = __float2half_rn(512.f * e89.x);
        __half h3 = __float2half_rn(512.f * e89.y);
        g_epack[(kt * KEMB + n) * 4 + qs] = make_uint2(pack_h2(h0, h1), pack_h2(h2, h3));
    }
}

// ---------------- main kernel ----------------
__global__ __launch_bounds__(NTHREADS)
void vq_mma_kernel(const float* __restrict__ lat,
                   const float* __restrict__ emb,
                   float* __restrict__ out /* d_out; quant = out+1 */)
{
    __shared__ float    BnS[KEMB];
    __shared__ float    AsS[TILE_M];
    __shared__ int      fbFlag[TILE_M];
    __shared__ unsigned long long mkey[TILE_M];
    __shared__ int      IdxS[TILE_M];
    __shared__ double   Wsum[4];
    __shared__ int      lastFlag;

    float* quant = out + 1;

    const int tid  = threadIdx.x;
    const int w    = tid >> 5;
    const int lane = tid & 31;
    const int qid  = lane >> 2;
    const int qsub = lane & 3;
    const int rowBase = blockIdx.x * TILE_M;

    #pragma unroll
    for (int i = 0; i < 4; i++) BnS[i * NTHREADS + tid] = g_bn[i * NTHREADS + tid];
    if (tid < TILE_M) {
        // a = ||x||^2: sequential fp32 chain (must match reference grid)
        const float* x = lat + (size_t)(rowBase + tid) * DDIM;
        float s = 0.f;
        #pragma unroll
        for (int d = 0; d < DDIM; d++)
            s = __fadd_rn(s, __fmul_rn(__ldg(x + d), __ldg(x + d)));
        AsS[tid] = s;
        fbFlag[tid] = 0;
        mkey[tid] = ~0ull;
    }

    // ---- A fragments: hi halves only (LDG + in-register convert) ----
    uint4 AH[KT];
    {
        const size_t r0 = (size_t)(rowBase + w * 16 + qid) * DDIM;
        const size_t r1 = r0 + 8 * DDIM;
        #pragma unroll
        for (int kt = 0; kt < KT; kt++) {
            const int k0 = kt * 16 + 2 * qsub;
            float2 x00 = __ldg((const float2*)(lat + r0 + k0));
            float2 x10 = __ldg((const float2*)(lat + r1 + k0));
            float2 x02 = __ldg((const float2*)(lat + r0 + k0 + 8));
            float2 x12 = __ldg((const float2*)(lat + r1 + k0 + 8));
            AH[kt] = make_uint4(
                pack_h2(__float2half_rn(x00.x), __float2half_rn(x00.y)),
                pack_h2(__float2half_rn(x10.x), __float2half_rn(x10.y)),
                pack_h2(__float2half_rn(x02.x), __float2half_rn(x02.y)),
                pack_h2(__float2half_rn(x12.x), __float2half_rn(x12.y)));
        }
    }
    __syncthreads();

    // ---- pass 1: 4 MMAs per nt; register top-3 per row ----
    float m1[2], m2[2], m3[2];
    int   i1[2], i2[2], i3[2];
    #pragma unroll
    for (int j = 0; j < 2; j++) {
        m1[j] = CUDART_INF_F; m2[j] = CUDART_INF_F; m3[j] = CUDART_INF_F;
        i1[j] = 0; i2[j] = 0; i3[j] = 0;
    }

    #pragma unroll 2
    for (int nt = 0; nt < NT_TILES; nt++) {
        uint2 Bc[KT];
        #pragma unroll
        for (int kt = 0; kt < KT; kt++)
            Bc[kt] = __ldg(&g_epack[(kt * KEMB + nt * 8 + qid) * 4 + qsub]);

        float s[4] = {0.f, 0.f, 0.f, 0.f};
        #pragma unroll
        for (int kt = 0; kt < KT; kt++)
            mma_f16(s, AH[kt], Bc[kt].x, Bc[kt].y);

        const int col0 = nt * 8 + qsub * 2;
        const float b0 = BnS[col0], b1 = BnS[col0 + 1];
        #pragma unroll
        for (int j = 0; j < 2; j++) {
            float h0 = __fmaf_rn(s[j * 2],     -0.00390625f, b0);
            float h1 = __fmaf_rn(s[j * 2 + 1], -0.00390625f, b1);
            // ascending col order: col0 then col0+1 (strict < keeps earlier)
            if (h0 < m1[j]) { m3[j]=m2[j]; i3[j]=i2[j]; m2[j]=m1[j]; i2[j]=i1[j]; m1[j]=h0; i1[j]=col0; }
            else if (h0 < m2[j]) { m3[j]=m2[j]; i3[j]=i2[j]; m2[j]=h0; i2[j]=col0; }
            else if (h0 < m3[j]) { m3[j]=h0; i3[j]=col0; }
            if (h1 < m1[j]) { m3[j]=m2[j]; i3[j]=i2[j]; m2[j]=m1[j]; i2[j]=i1[j]; m1[j]=h1; i1[j]=col0+1; }
            else if (h1 < m2[j]) { m3[j]=m2[j]; i3[j]=i2[j]; m2[j]=h1; i2[j]=col0+1; }
            else if (h1 < m3[j]) { m3[j]=h1; i3[j]=col0+1; }
        }
    }

    // ---- per row: quad gmin, coverage check, rescore or flag fallback ----
    #pragma unroll
    for (int j = 0; j < 2; j++) {
        const int rowL = w * 16 + j * 8 + qid;
        float g = m1[j];
        g = fminf(g, __shfl_xor_sync(0xffffffffu, g, 1));
        g = fminf(g, __shfl_xor_sync(0xffffffffu, g, 2));
        const float thr = g + BAND;
        int fb = (m3[j] < thr) ? 1 : 0;
        fb |= __shfl_xor_sync(0xffffffffu, fb, 1);
        fb |= __shfl_xor_sync(0xffffffffu, fb, 2);
        if (fb) {
            if (qsub == 0) fbFlag[rowL] = 1;
        } else {
            const float* xr = lat + (size_t)(rowBase + rowL) * DDIM;
            const float aR = AsS[rowL];
            if (m1[j] <= thr) {
                float d = exact_dist4(xr, emb + (size_t)i1[j] * DDIM, aR, BnS[i1[j]]);
                atomicMin(&mkey[rowL],
                    ((unsigned long long)__float_as_uint(d) << 32) | (unsigned)i1[j]);
            }
            if (m2[j] <= thr) {
                float d = exact_dist4(xr, emb + (size_t)i2[j] * DDIM, aR, BnS[i2[j]]);
                atomicMin(&mkey[rowL],
                    ((unsigned long long)__float_as_uint(d) << 32) | (unsigned)i2[j]);
            }
        }
    }
    __syncthreads();

    // ---- fallback: exact full rescan for flagged rows (sound superset) ----
    for (int r = 0; r < TILE_M; r++) {
        if (fbFlag[r]) {
            const float* xr = lat + (size_t)(rowBase + r) * DDIM;
            const float aR = AsS[r];
            for (int col = tid; col < KEMB; col += NTHREADS) {
                float d = exact_dist4(xr, emb + (size_t)col * DDIM, aR, BnS[col]);
                atomicMin(&mkey[r],
                    ((unsigned long long)__float_as_uint(d) << 32) | (unsigned)col);
            }
        }
    }
    __syncthreads();
    if (tid < TILE_M) IdxS[tid] = (int)(mkey[tid] & 0xFFFFFFFFull);
    __syncthreads();

    // ---- gather + straight-through write (scalar stores) + fp64 loss ----
    double ls = 0.0;
    {
        const int seg  = tid & 15;
        const int rsub = tid >> 4;
        #pragma unroll
        for (int p = 0; p < 8; p++) {
            int row = p * 8 + rsub;
            int idx = IdxS[row];
            float4 q = __ldg((const float4*)(emb + (size_t)idx * DDIM + seg * 4));
            float4 l = __ldg((const float4*)(lat + (size_t)(rowBase + row) * DDIM + seg * 4));
            float t0 = q.x - l.x, t1 = q.y - l.y, t2 = q.z - l.z, t3 = q.w - l.w;
            ls += (double)t0 * t0 + (double)t1 * t1
                + (double)t2 * t2 + (double)t3 * t3;
            float* o = quant + (size_t)(rowBase + row) * DDIM + seg * 4;
            o[0] = l.x + t0;
            o[1] = l.y + t1;
            o[2] = l.z + t2;
            o[3] = l.w + t3;
        }
    }

    #pragma unroll
    for (int off = 16; off >= 1; off >>= 1)
        ls += __shfl_xor_sync(0xffffffffu, ls, off);
    if (lane == 0) Wsum[w] = ls;
    __syncthreads();

    // ---- publish partial, then last CTA reduces (deterministic order) ----
    if (tid == 0) {
        g_part[blockIdx.x] = Wsum[0] + Wsum[1] + Wsum[2] + Wsum[3];
        __threadfence();
        int ticket = atomicAdd(&g_cnt, 1);
        lastFlag = (ticket == NCTAS - 1) ? 1 : 0;
    }
    __syncthreads();
    if (lastFlag) {
        double s = 0.0;
        #pragma unroll
        for (int i = 0; i < NCTAS / NTHREADS; i++)     // fixed order: 8 per thread
            s += g_part[i * NTHREADS + tid];
        #pragma unroll
        for (int off = 16; off >= 1; off >>= 1)
            s += __shfl_xor_sync(0xffffffffu, s, off);
        if (lane == 0) Wsum[w] = s;
        __syncthreads();
        if (tid == 0) {
            double m = (Wsum[0] + Wsum[1] + Wsum[2] + Wsum[3])
                       / (double)((size_t)NROWS * DDIM);
            out[0] = (float)(1.25 * m);
            g_cnt = 0;   // self-reset for graph replay
        }
    }
}

extern "C" void kernel_launch(void* const* d_in, const int* in_sizes, int n_in,
                              void* d_out, int out_size) {
    const float* lat = (const float*)d_in[0];   // latents  [65536, 64]
    const float* emb = (const float*)d_in[1];   // embedding [512, 64]
    float* out = (float*)d_out;

    vq_epack_kernel<<<8, 128>>>(emb);
    vq_mma_kernel<<<NCTAS, NTHREADS>>>(lat, emb, out);
}